// round 2
// baseline (speedup 1.0000x reference)
#include <cuda_runtime.h>
#include <cuda_bf16.h>
#include <cstdint>

// Problem dims (fixed by the dataset)
#define BATCH  16
#define SEQ    1024
#define HDIM   1024
#define ELEMS_PER_MAT (16777216LL)   // 16*1024*1024

// Intermediate scratch (device globals; no allocation allowed)
__device__ float g_q[ELEMS_PER_MAT];
__device__ float g_k[ELEMS_PER_MAT];
__device__ float g_v[ELEMS_PER_MAT];
__device__ float g_p[ELEMS_PER_MAT];

static const int BM = 128, BN = 128, BK = 32;

// Bank-conflict-free swizzle: row-stride 32 words, permute k within row.
__device__ __forceinline__ int swz(int r, int k) {
    return r * 32 + (k ^ ((r & 7) << 2) ^ ((r >> 3) & 3));
}

__device__ __forceinline__ uint32_t f2tf(float x) {
    uint32_t r;
    asm("cvt.rna.tf32.f32 %0, %1;" : "=r"(r) : "f"(x));
    return r;
}

__device__ __forceinline__ void mma_tf32(float c[4], const uint32_t a[4], const uint32_t b[2]) {
    asm volatile(
        "mma.sync.aligned.m16n8k8.row.col.f32.tf32.tf32.f32 "
        "{%0,%1,%2,%3}, {%4,%5,%6,%7}, {%8,%9}, {%0,%1,%2,%3};\n"
        : "+f"(c[0]), "+f"(c[1]), "+f"(c[2]), "+f"(c[3])
        : "r"(a[0]), "r"(a[1]), "r"(a[2]), "r"(a[3]), "r"(b[0]), "r"(b[1]));
}

// TA: 0 = A row-major [m][k]; 1 = A transposed, element (m,k) at A[k*lda + m]
// TB: 0 = B row-major [k][n]; 1 = B transposed, element (k,n) at B[n*ldb + k]
// EPI: 0 = +bias[n]; 1 = *scale; 2 = plain
template <int TA, int TB, int EPI>
__global__ __launch_bounds__(256, 2)
void gemm_tf32(const float* __restrict__ A, const float* __restrict__ B,
               float* __restrict__ C,
               int lda, int ldb, int ldc, int K,
               const float* __restrict__ bias, float scale,
               long long sA, long long sB, long long sC)
{
    A += (long long)blockIdx.z * sA;
    B += (long long)blockIdx.z * sB;
    C += (long long)blockIdx.z * sC;

    const int m0 = blockIdx.y * BM;
    const int n0 = blockIdx.x * BN;

    __shared__ uint32_t As[BM * BK];
    __shared__ uint32_t Bs[BN * BK];

    const int tid  = threadIdx.x;
    const int lane = tid & 31;
    const int warp = tid >> 5;
    const int wm0  = (warp >> 2) * 64;   // 2 warps in M
    const int wn0  = (warp & 3) * 32;    // 4 warps in N
    const int g    = lane >> 2;          // groupID
    const int t    = lane & 3;           // threadID in group

    float acc[4][4][4];
#pragma unroll
    for (int i = 0; i < 4; i++)
#pragma unroll
        for (int j = 0; j < 4; j++)
#pragma unroll
            for (int r = 0; r < 4; r++) acc[i][j][r] = 0.0f;

    for (int k0 = 0; k0 < K; k0 += BK) {
        // ---- load A tile (BM x BK) ----
        if (TA == 0) {
            int k = tid & 31, m = tid >> 5;
#pragma unroll
            for (int i = 0; i < 16; i++, m += 8)
                As[swz(m, k)] = f2tf(A[(long long)(m0 + m) * lda + (k0 + k)]);
        } else {
            int m = tid & 127, k = tid >> 7;
#pragma unroll
            for (int i = 0; i < 16; i++, k += 2)
                As[swz(m, k)] = f2tf(A[(long long)(k0 + k) * lda + (m0 + m)]);
        }
        // ---- load B tile (BN x BK), stored n-major ----
        if (TB == 0) {
            int n = tid & 127, k = tid >> 7;
#pragma unroll
            for (int i = 0; i < 16; i++, k += 2)
                Bs[swz(n, k)] = f2tf(B[(long long)(k0 + k) * ldb + (n0 + n)]);
        } else {
            int k = tid & 31, n = tid >> 5;
#pragma unroll
            for (int i = 0; i < 16; i++, n += 8)
                Bs[swz(n, k)] = f2tf(B[(long long)(n0 + n) * ldb + (k0 + k)]);
        }
        __syncthreads();

#pragma unroll
        for (int kk = 0; kk < BK; kk += 8) {
            uint32_t af[4][4], bf[4][2];
#pragma unroll
            for (int mt = 0; mt < 4; mt++) {
                int m = wm0 + mt * 16;
                af[mt][0] = As[swz(m + g,     kk + t)];
                af[mt][1] = As[swz(m + g + 8, kk + t)];
                af[mt][2] = As[swz(m + g,     kk + t + 4)];
                af[mt][3] = As[swz(m + g + 8, kk + t + 4)];
            }
#pragma unroll
            for (int nt = 0; nt < 4; nt++) {
                int n = wn0 + nt * 8;
                bf[nt][0] = Bs[swz(n + g, kk + t)];
                bf[nt][1] = Bs[swz(n + g, kk + t + 4)];
            }
#pragma unroll
            for (int mt = 0; mt < 4; mt++)
#pragma unroll
                for (int nt = 0; nt < 4; nt++)
                    mma_tf32(acc[mt][nt], af[mt], bf[nt]);
        }
        __syncthreads();
    }

    // ---- epilogue ----
#pragma unroll
    for (int mt = 0; mt < 4; mt++)
#pragma unroll
        for (int nt = 0; nt < 4; nt++) {
            int row = m0 + wm0 + mt * 16 + g;
            int col = n0 + wn0 + nt * 8 + 2 * t;
            float v0 = acc[mt][nt][0], v1 = acc[mt][nt][1];
            float v2 = acc[mt][nt][2], v3 = acc[mt][nt][3];
            if (EPI == 0) {
                float b0 = __ldg(&bias[col]), b1 = __ldg(&bias[col + 1]);
                v0 += b0; v1 += b1; v2 += b0; v3 += b1;
            }
            if (EPI == 1) { v0 *= scale; v1 *= scale; v2 *= scale; v3 *= scale; }
            *(float2*)&C[(long long)row * ldc + col]       = make_float2(v0, v1);
            *(float2*)&C[(long long)(row + 8) * ldc + col] = make_float2(v2, v3);
        }
}

// Row-wise softmax over P[row][0..1023]. Row = b*1024 + g; mask[b,g]==0 -> NaN row
// (matches jax: softmax over an all -inf column is NaN).
__global__ void softmax_rows(float* __restrict__ P, const int* __restrict__ mask)
{
    const int row = blockIdx.x;
    float* p = P + (long long)row * 1024;
    const int tid = threadIdx.x;

    if (mask[row] == 0) {
        float nanv = __int_as_float(0x7fc00000);
#pragma unroll
        for (int i = 0; i < 4; i++) p[tid + 256 * i] = nanv;
        return;
    }

    float v[4];
    float mx = -INFINITY;
#pragma unroll
    for (int i = 0; i < 4; i++) {
        v[i] = p[tid + 256 * i];
        mx = fmaxf(mx, v[i]);
    }
    __shared__ float smax[8], ssum[8];
#pragma unroll
    for (int o = 16; o; o >>= 1) mx = fmaxf(mx, __shfl_xor_sync(0xffffffffu, mx, o));
    if ((tid & 31) == 0) smax[tid >> 5] = mx;
    __syncthreads();
    mx = smax[0];
#pragma unroll
    for (int w = 1; w < 8; w++) mx = fmaxf(mx, smax[w]);

    float s = 0.0f;
#pragma unroll
    for (int i = 0; i < 4; i++) {
        v[i] = __expf(v[i] - mx);
        s += v[i];
    }
#pragma unroll
    for (int o = 16; o; o >>= 1) s += __shfl_xor_sync(0xffffffffu, s, o);
    if ((tid & 31) == 0) ssum[tid >> 5] = s;
    __syncthreads();
    s = ssum[0];
#pragma unroll
    for (int w = 1; w < 8; w++) s += ssum[w];

    float r = __fdividef(1.0f, s);
#pragma unroll
    for (int i = 0; i < 4; i++) p[tid + 256 * i] = v[i] * r;
}

extern "C" void kernel_launch(void* const* d_in, const int* in_sizes, int n_in,
                              void* d_out, int out_size)
{
    const float* X    = (const float*)d_in[0];
    const int*   mask = (const int*)  d_in[1];
    const float* wq   = (const float*)d_in[2];
    const float* bq   = (const float*)d_in[3];
    const float* wk   = (const float*)d_in[4];
    const float* bk   = (const float*)d_in[5];
    const float* wv   = (const float*)d_in[6];
    const float* bv   = (const float*)d_in[7];
    float* out = (float*)d_out;

    void *pq, *pk, *pv, *pp;
    cudaGetSymbolAddress(&pq, g_q);
    cudaGetSymbolAddress(&pk, g_k);
    cudaGetSymbolAddress(&pv, g_v);
    cudaGetSymbolAddress(&pp, g_p);
    float* Q = (float*)pq;
    float* Kb = (float*)pk;
    float* V = (float*)pv;
    float* P = (float*)pp;

    const long long MS = 1024LL * 1024LL;  // per-batch matrix stride

    // 1) QKV projections: [16384,1024] x [1024,1024] + bias
    dim3 gproj(HDIM / BN, (BATCH * SEQ) / BM, 1);
    gemm_tf32<0, 0, 0><<<gproj, 256>>>(X, wq, Q,  1024, 1024, 1024, 1024, bq, 1.0f, 0, 0, 0);
    gemm_tf32<0, 0, 0><<<gproj, 256>>>(X, wk, Kb, 1024, 1024, 1024, 1024, bk, 1.0f, 0, 0, 0);
    gemm_tf32<0, 0, 0><<<gproj, 256>>>(X, wv, V,  1024, 1024, 1024, 1024, bv, 1.0f, 0, 0, 0);

    // 2) P[g,h] = (1/32) * sum_s Q[s,g] * K[s,h]   (scores transposed)
    dim3 gatt(HDIM / BN, HDIM / BM, BATCH);
    gemm_tf32<1, 0, 1><<<gatt, 256>>>(Q, Kb, P, 1024, 1024, 1024, 1024, nullptr, 0.03125f, MS, MS, MS);

    // 3) Row-wise softmax of P (== softmax over h of scores[h,g])
    softmax_rows<<<BATCH * HDIM, 256>>>(P, mask);

    // 4) out[s,g] = sum_h V[s,h] * P[g,h]
    gemm_tf32<0, 1, 2><<<gatt, 256>>>(V, P, out, 1024, 1024, 1024, 1024, nullptr, 1.0f, MS, MS, MS);
}

// round 3
// speedup vs baseline: 1.0473x; 1.0473x over previous
#include <cuda_runtime.h>
#include <cuda_bf16.h>
#include <cstdint>

// Problem dims (fixed by the dataset)
#define BATCH  16
#define SEQ    1024
#define HDIM   1024
#define ELEMS_PER_MAT (16777216LL)   // 16*1024*1024

// Scratch (device globals; no allocation allowed)
__device__ float g_x [ELEMS_PER_MAT];   // X rounded to tf32
__device__ float g_wq[1048576];         // Wq^T rounded
__device__ float g_wk[1048576];
__device__ float g_wv[1048576];
__device__ float g_q [ELEMS_PER_MAT];
__device__ float g_k [ELEMS_PER_MAT];
__device__ float g_v [ELEMS_PER_MAT];
__device__ float g_qt[ELEMS_PER_MAT];
__device__ float g_kt[ELEMS_PER_MAT];
__device__ float g_p [ELEMS_PER_MAT];

static const int BM = 128, BN = 128, BK = 32;
static const int STAGES = 3;
static const int STAGE_WORDS = 2 * BM * BK;          // A + B tiles = 8192 words
static const int SMEM_BYTES  = STAGES * STAGE_WORDS * 4;  // 98304

__device__ __forceinline__ float tf32f(float x) {
    uint32_t r;
    asm("cvt.rna.tf32.f32 %0, %1;" : "=r"(r) : "f"(x));
    return __uint_as_float(r);
}

__device__ __forceinline__ void cpa16(uint32_t dst, const void* src) {
    asm volatile("cp.async.cg.shared.global [%0], [%1], 16;" :: "r"(dst), "l"(src));
}
__device__ __forceinline__ void cpa_commit() {
    asm volatile("cp.async.commit_group;");
}
template <int N>
__device__ __forceinline__ void cpa_wait() {
    asm volatile("cp.async.wait_group %0;" :: "n"(N));
}

__device__ __forceinline__ void mma_tf32(float c[4], const uint32_t a[4], const uint32_t b[2]) {
    asm volatile(
        "mma.sync.aligned.m16n8k8.row.col.f32.tf32.tf32.f32 "
        "{%0,%1,%2,%3}, {%4,%5,%6,%7}, {%8,%9}, {%0,%1,%2,%3};\n"
        : "+f"(c[0]), "+f"(c[1]), "+f"(c[2]), "+f"(c[3])
        : "r"(a[0]), "r"(a[1]), "r"(a[2]), "r"(a[3]), "r"(b[0]), "r"(b[1]));
}

// Uniform GEMM: A row-major [M][K] (k contiguous), B n-major [N][K] (k contiguous),
// C row-major [M][N].  All inputs pre-rounded to tf32; no cvt inside.
// Smem tile layout: row r (m or n) = 32 words; 16B chunk c (=k>>2) stored at
// chunk slot (c ^ (r&7)).  Word (r,k) lives at  r*32 + ((k&~3) ^ ((r&7)<<2)) + (k&3).
// EPI: 0 = +bias[n], round to tf32; 1 = *scale (no round); 2 = plain (no round)
template <int EPI>
__global__ __launch_bounds__(256, 2)
void gemm_tf32(const float* __restrict__ A, const float* __restrict__ B,
               float* __restrict__ C,
               int lda, int ldb, int ldc, int K,
               const float* __restrict__ bias, float scale,
               long long sA, long long sB, long long sC)
{
    extern __shared__ float sm[];

    A += (long long)blockIdx.z * sA;
    B += (long long)blockIdx.z * sB;
    C += (long long)blockIdx.z * sC;

    const int m0 = blockIdx.y * BM;
    const int n0 = blockIdx.x * BN;

    const int tid  = threadIdx.x;
    const int lane = tid & 31;
    const int warp = tid >> 5;
    const int wm0  = (warp >> 2) * 64;   // 2 warps in M
    const int wn0  = (warp & 3) * 32;    // 4 warps in N
    const int g    = lane >> 2;
    const int t    = lane & 3;

    // ---- loader coords: each thread copies 4 chunks of A and 4 of B ----
    const int lm  = tid >> 1;            // row within tile (0..127)
    const int lc0 = (tid & 1) * 4;       // first chunk (0..7)
    const float* Ag = A + (long long)(m0 + lm) * lda;
    const float* Bg = B + (long long)(n0 + lm) * ldb;
    int adst[4];
#pragma unroll
    for (int i = 0; i < 4; i++)
        adst[i] = lm * 32 + (((lc0 + i) ^ (lm & 7)) << 2);

    // ---- fragment read bases (byte-free, word indices) ----
    int baseA[8];   // [mt*2 + half]
#pragma unroll
    for (int mt = 0; mt < 4; mt++)
#pragma unroll
        for (int h = 0; h < 2; h++) {
            int m = wm0 + mt * 16 + h * 8 + g;
            baseA[mt * 2 + h] = m * 32 + ((m & 7) << 2) + t;
        }
    int baseB[4];
#pragma unroll
    for (int nt = 0; nt < 4; nt++) {
        int n = wn0 + nt * 8 + g;
        baseB[nt] = n * 32 + ((n & 7) << 2) + t;
    }

    float acc[4][4][4];
#pragma unroll
    for (int i = 0; i < 4; i++)
#pragma unroll
        for (int j = 0; j < 4; j++)
#pragma unroll
            for (int r = 0; r < 4; r++) acc[i][j][r] = 0.0f;

    // issue one stage's loads
    auto issue = [&](int stage, int k0) {
        float* sa = sm + stage * STAGE_WORDS;
        float* sb = sa + BM * BK;
#pragma unroll
        for (int i = 0; i < 4; i++) {
            int koff = k0 + (lc0 + i) * 4;
            cpa16((uint32_t)__cvta_generic_to_shared(sa + adst[i]), Ag + koff);
            cpa16((uint32_t)__cvta_generic_to_shared(sb + adst[i]), Bg + koff);
        }
    };

    const int NIT = K / BK;
    issue(0, 0);  cpa_commit();
    issue(1, BK); cpa_commit();
    int knext = 2 * BK;

    for (int it = 0; it < NIT; ++it) {
        cpa_wait<STAGES - 2>();
        __syncthreads();

        int ns = it + (STAGES - 1);
        if (knext < K) issue(ns >= STAGES ? ns - STAGES * (ns / STAGES) : ns, knext);
        cpa_commit();
        knext += BK;

        const int st = it % STAGES;
        const float* sa = sm + st * STAGE_WORDS;
        const float* sb = sa + BM * BK;

#pragma unroll
        for (int kk = 0; kk < BK; kk += 8) {
            uint32_t af[4][4], bf[4][2];
#pragma unroll
            for (int mt = 0; mt < 4; mt++) {
                af[mt][0] = __float_as_uint(sa[baseA[mt * 2]     ^ kk]);
                af[mt][1] = __float_as_uint(sa[baseA[mt * 2 + 1] ^ kk]);
                af[mt][2] = __float_as_uint(sa[baseA[mt * 2]     ^ (kk + 4)]);
                af[mt][3] = __float_as_uint(sa[baseA[mt * 2 + 1] ^ (kk + 4)]);
            }
#pragma unroll
            for (int nt = 0; nt < 4; nt++) {
                bf[nt][0] = __float_as_uint(sb[baseB[nt] ^ kk]);
                bf[nt][1] = __float_as_uint(sb[baseB[nt] ^ (kk + 4)]);
            }
#pragma unroll
            for (int mt = 0; mt < 4; mt++)
#pragma unroll
                for (int nt = 0; nt < 4; nt++)
                    mma_tf32(acc[mt][nt], af[mt], bf[nt]);
        }
        __syncthreads();
    }

    // ---- epilogue ----
#pragma unroll
    for (int mt = 0; mt < 4; mt++)
#pragma unroll
        for (int nt = 0; nt < 4; nt++) {
            int row = m0 + wm0 + mt * 16 + g;
            int col = n0 + wn0 + nt * 8 + 2 * t;
            float v0 = acc[mt][nt][0], v1 = acc[mt][nt][1];
            float v2 = acc[mt][nt][2], v3 = acc[mt][nt][3];
            if (EPI == 0) {
                float b0 = __ldg(&bias[col]), b1 = __ldg(&bias[col + 1]);
                v0 = tf32f(v0 + b0); v1 = tf32f(v1 + b1);
                v2 = tf32f(v2 + b0); v3 = tf32f(v3 + b1);
            }
            if (EPI == 1) { v0 *= scale; v1 *= scale; v2 *= scale; v3 *= scale; }
            *(float2*)&C[(long long)row * ldc + col]       = make_float2(v0, v1);
            *(float2*)&C[(long long)(row + 8) * ldc + col] = make_float2(v2, v3);
        }
}

// Round 16M floats to tf32 (vectorized)
__global__ void round_tf32_k(const float4* __restrict__ in, float4* __restrict__ out)
{
    long long i = (long long)blockIdx.x * blockDim.x + threadIdx.x;
    float4 v = in[i];
    v.x = tf32f(v.x); v.y = tf32f(v.y); v.z = tf32f(v.z); v.w = tf32f(v.w);
    out[i] = v;
}

// Transpose 1024x1024 (per z) with tf32 rounding (idempotent on rounded data)
__global__ void transpose_rnd(const float* __restrict__ in, float* __restrict__ out)
{
    __shared__ float tile[32][33];
    long long base = (long long)blockIdx.z * 1048576LL;
    int x = blockIdx.x * 32 + threadIdx.x;
    int y = blockIdx.y * 32 + threadIdx.y;
#pragma unroll
    for (int j = 0; j < 32; j += 8)
        tile[threadIdx.y + j][threadIdx.x] = in[base + (long long)(y + j) * 1024 + x];
    __syncthreads();
    x = blockIdx.y * 32 + threadIdx.x;
    y = blockIdx.x * 32 + threadIdx.y;
#pragma unroll
    for (int j = 0; j < 32; j += 8)
        out[base + (long long)(y + j) * 1024 + x] = tf32f(tile[threadIdx.x][threadIdx.y + j]);
}

// Row-wise softmax over P[row][0..1023]; output rounded to tf32.
// row = b*1024 + g; mask[b,g]==0 -> NaN row (matches jax all -inf column softmax).
__global__ void softmax_rows(float* __restrict__ P, const int* __restrict__ mask)
{
    const int row = blockIdx.x;
    float* p = P + (long long)row * 1024;
    const int tid = threadIdx.x;

    if (mask[row] == 0) {
        float nanv = __int_as_float(0x7fc00000);
#pragma unroll
        for (int i = 0; i < 4; i++) p[tid + 256 * i] = nanv;
        return;
    }

    float v[4];
    float mx = -INFINITY;
#pragma unroll
    for (int i = 0; i < 4; i++) {
        v[i] = p[tid + 256 * i];
        mx = fmaxf(mx, v[i]);
    }
    __shared__ float smax[8], ssum[8];
#pragma unroll
    for (int o = 16; o; o >>= 1) mx = fmaxf(mx, __shfl_xor_sync(0xffffffffu, mx, o));
    if ((tid & 31) == 0) smax[tid >> 5] = mx;
    __syncthreads();
    mx = smax[0];
#pragma unroll
    for (int w = 1; w < 8; w++) mx = fmaxf(mx, smax[w]);

    float s = 0.0f;
#pragma unroll
    for (int i = 0; i < 4; i++) {
        v[i] = __expf(v[i] - mx);
        s += v[i];
    }
#pragma unroll
    for (int o = 16; o; o >>= 1) s += __shfl_xor_sync(0xffffffffu, s, o);
    if ((tid & 31) == 0) ssum[tid >> 5] = s;
    __syncthreads();
    s = ssum[0];
#pragma unroll
    for (int w = 1; w < 8; w++) s += ssum[w];

    float r = __fdividef(1.0f, s);
#pragma unroll
    for (int i = 0; i < 4; i++) p[tid + 256 * i] = tf32f(v[i] * r);
}

extern "C" void kernel_launch(void* const* d_in, const int* in_sizes, int n_in,
                              void* d_out, int out_size)
{
    const float* X    = (const float*)d_in[0];
    const int*   mask = (const int*)  d_in[1];
    const float* wq   = (const float*)d_in[2];
    const float* bq   = (const float*)d_in[3];
    const float* wk   = (const float*)d_in[4];
    const float* bk   = (const float*)d_in[5];
    const float* wv   = (const float*)d_in[6];
    const float* bv   = (const float*)d_in[7];
    float* out = (float*)d_out;

    void *px, *pwq, *pwk, *pwv, *pq, *pk, *pv, *pqt, *pkt, *pp;
    cudaGetSymbolAddress(&px,  g_x);
    cudaGetSymbolAddress(&pwq, g_wq);
    cudaGetSymbolAddress(&pwk, g_wk);
    cudaGetSymbolAddress(&pwv, g_wv);
    cudaGetSymbolAddress(&pq,  g_q);
    cudaGetSymbolAddress(&pk,  g_k);
    cudaGetSymbolAddress(&pv,  g_v);
    cudaGetSymbolAddress(&pqt, g_qt);
    cudaGetSymbolAddress(&pkt, g_kt);
    cudaGetSymbolAddress(&pp,  g_p);
    float* Xr  = (float*)px;
    float* Wqt = (float*)pwq;
    float* Wkt = (float*)pwk;
    float* Wvt = (float*)pwv;
    float* Q   = (float*)pq;
    float* Kb  = (float*)pk;
    float* V   = (float*)pv;
    float* Qt  = (float*)pqt;
    float* Kt  = (float*)pkt;
    float* P   = (float*)pp;

    cudaFuncSetAttribute(gemm_tf32<0>, cudaFuncAttributeMaxDynamicSharedMemorySize, SMEM_BYTES);
    cudaFuncSetAttribute(gemm_tf32<1>, cudaFuncAttributeMaxDynamicSharedMemorySize, SMEM_BYTES);
    cudaFuncSetAttribute(gemm_tf32<2>, cudaFuncAttributeMaxDynamicSharedMemorySize, SMEM_BYTES);

    const long long MS = 1024LL * 1024LL;

    // 0) pre-round X; transpose+round weights (-> k-contiguous B operands)
    round_tf32_k<<<16384, 256>>>((const float4*)X, (float4*)Xr);
    {
        dim3 gt(32, 32, 1), bt(32, 8);
        transpose_rnd<<<gt, bt>>>(wq, Wqt);
        transpose_rnd<<<gt, bt>>>(wk, Wkt);
        transpose_rnd<<<gt, bt>>>(wv, Wvt);
    }

    // 1) QKV projections: [16384,1024] x Wt[1024,1024] + bias, rounded outputs
    dim3 gproj(HDIM / BN, (BATCH * SEQ) / BM, 1);
    gemm_tf32<0><<<gproj, 256, SMEM_BYTES>>>(Xr, Wqt, Q,  1024, 1024, 1024, 1024, bq, 1.0f, 0, 0, 0);
    gemm_tf32<0><<<gproj, 256, SMEM_BYTES>>>(Xr, Wkt, Kb, 1024, 1024, 1024, 1024, bk, 1.0f, 0, 0, 0);
    gemm_tf32<0><<<gproj, 256, SMEM_BYTES>>>(Xr, Wvt, V,  1024, 1024, 1024, 1024, bv, 1.0f, 0, 0, 0);

    // 1b) transpose Q,K per batch (-> s-contiguous for the reduction over s)
    {
        dim3 gt(32, 32, BATCH), bt(32, 8);
        transpose_rnd<<<gt, bt>>>(Q,  Qt);
        transpose_rnd<<<gt, bt>>>(Kb, Kt);
    }

    // 2) P[g,h] = (1/32) * sum_s Qt[g,s] * Kt[h,s]   (scores transposed)
    dim3 gatt(HDIM / BN, HDIM / BM, BATCH);
    gemm_tf32<1><<<gatt, 256, SMEM_BYTES>>>(Qt, Kt, P, 1024, 1024, 1024, 1024, nullptr, 0.03125f, MS, MS, MS);

    // 3) Row-wise softmax of P (== softmax over h of scores[h,g]); rounds output
    softmax_rows<<<BATCH * HDIM, 256>>>(P, mask);

    // 4) out[s,g] = sum_h V[s,h] * P[g,h]
    gemm_tf32<2><<<gatt, 256, SMEM_BYTES>>>(V, P, out, 1024, 1024, 1024, 1024, nullptr, 1.0f, MS, MS, MS);
}